// round 3
// baseline (speedup 1.0000x reference)
#include <cuda_runtime.h>
#include <cstddef>

// Problem constants
#define DD   128
#define NB   4
#define NSRC 10000
#define NTGT 10000
#define NE   160000
#define NK   16

// Scratch (device globals: allocation-free rule)
__device__ float g_sproj [NB * NSRC * DD];         // src @ W_s2e
__device__ float g_tproj [NB * NTGT * DD];         // tgt @ W_t2e
__device__ float g_tproj2[NB * NTGT * DD];         // tgt @ W_t2t
__device__ float g_dbond [NB * NE * DD];           // normalized bond delta (327 MB)

// Tiling: 256 threads = 8 warps; each warp owns 8 rows x (4 cols per lane).
#define ROWS_PER_WARP 8
#define ROWS_PER_BLK  64
#define SMEM_FLOATS   (DD * DD + ROWS_PER_BLK * DD)   // W (16384) + X tile (8192)

__device__ __forceinline__ float silu_f(float x) {
    return x / (1.0f + __expf(-x));
}

__device__ __forceinline__ void load_w_smem(float* Ws, const float* __restrict__ W, int tid) {
    const float4* src = reinterpret_cast<const float4*>(W);
    float4* dst = reinterpret_cast<float4*>(Ws);
#pragma unroll
    for (int i = 0; i < 16; ++i)            // 4096 float4 / 256 threads
        dst[tid + i * 256] = src[tid + i * 256];
}

__device__ __forceinline__ void load_x_smem(float* Xs, const float* __restrict__ Xrows, int tid) {
    const float4* src = reinterpret_cast<const float4*>(Xrows);
    float4* dst = reinterpret_cast<float4*>(Xs);
#pragma unroll
    for (int i = 0; i < 8; ++i)             // 2048 float4 / 256 threads
        dst[tid + i * 256] = src[tid + i * 256];
}

// Y_tile[r][lane*4+c] = sum_k X_tile[r][k] * W[k][lane*4+c]
__device__ __forceinline__ void gemm_tile(const float* __restrict__ Ws,
                                          const float* __restrict__ Xs,
                                          int wrow0, int lane, float4 acc[ROWS_PER_WARP]) {
#pragma unroll
    for (int r = 0; r < ROWS_PER_WARP; ++r) acc[r] = make_float4(0.f, 0.f, 0.f, 0.f);
#pragma unroll 4
    for (int k = 0; k < DD; ++k) {
        float4 wv = reinterpret_cast<const float4*>(Ws + k * DD)[lane];
#pragma unroll
        for (int r = 0; r < ROWS_PER_WARP; ++r) {
            float xv = Xs[(wrow0 + r) * DD + k];     // warp-broadcast LDS
            acc[r].x += xv * wv.x;
            acc[r].y += xv * wv.y;
            acc[r].z += xv * wv.z;
            acc[r].w += xv * wv.w;
        }
    }
}

// In-warp LayerNorm over 128 values (4 per lane). Returns mean/rstd to all lanes.
__device__ __forceinline__ void warp_ln_stats(float z0, float z1, float z2, float z3,
                                              float& mean, float& rstd) {
    float s  = z0 + z1 + z2 + z3;
    float s2 = z0 * z0 + z1 * z1 + z2 * z2 + z3 * z3;
#pragma unroll
    for (int off = 16; off; off >>= 1) {
        s  += __shfl_xor_sync(0xffffffffu, s,  off);
        s2 += __shfl_xor_sync(0xffffffffu, s2, off);
    }
    mean = s * (1.0f / DD);
    float var = s2 * (1.0f / DD) - mean * mean;
    rstd = rsqrtf(var + 1e-5f);
}

// ---------------- Kernel 1: plain Y = X @ W (row-major 128x128 weight) --------
extern "C" __global__ void __launch_bounds__(256, 2)
k_gemm128(const float* __restrict__ X, const float* __restrict__ W, float* __restrict__ Y) {
    extern __shared__ float sm[];
    float* Ws = sm;
    float* Xs = sm + DD * DD;
    const int tid = threadIdx.x, lane = tid & 31, warp = tid >> 5;
    const size_t rowBase = (size_t)blockIdx.x * ROWS_PER_BLK;

    load_w_smem(Ws, W, tid);
    load_x_smem(Xs, X + rowBase * DD, tid);
    __syncthreads();

    float4 acc[ROWS_PER_WARP];
    gemm_tile(Ws, Xs, warp * ROWS_PER_WARP, lane, acc);

#pragma unroll
    for (int r = 0; r < ROWS_PER_WARP; ++r) {
        size_t row = rowBase + warp * ROWS_PER_WARP + r;
        reinterpret_cast<float4*>(Y + row * DD)[lane] = acc[r];
    }
}

// ---------------- Kernel 2: bond update ---------------------------------------
// d_bond = LN(silu(bond@W_e2e + sproj[src_order] + tproj[tgt_order]))
// out_bond = bond + d_bond ; also store d_bond to scratch.
extern "C" __global__ void __launch_bounds__(256, 2)
k_bond(const float* __restrict__ bond, const float* __restrict__ W,
       const int* __restrict__ src_order, const int* __restrict__ tgt_order,
       const float* __restrict__ ln_g, const float* __restrict__ ln_b,
       float* __restrict__ out_bond) {
    extern __shared__ float sm[];
    float* Ws = sm;
    float* Xs = sm + DD * DD;
    const int tid = threadIdx.x, lane = tid & 31, warp = tid >> 5;
    const size_t rowBase = (size_t)blockIdx.x * ROWS_PER_BLK;   // rows = b*NE + e

    load_w_smem(Ws, W, tid);
    load_x_smem(Xs, bond + rowBase * DD, tid);
    __syncthreads();

    float4 acc[ROWS_PER_WARP];
    gemm_tile(Ws, Xs, warp * ROWS_PER_WARP, lane, acc);

    const float4 gv = reinterpret_cast<const float4*>(ln_g)[lane];
    const float4 bv = reinterpret_cast<const float4*>(ln_b)[lane];

#pragma unroll
    for (int r = 0; r < ROWS_PER_WARP; ++r) {
        size_t row = rowBase + warp * ROWS_PER_WARP + r;
        int b = (int)(row / NE);
        int e = (int)(row - (size_t)b * NE);
        int so = __ldg(src_order + e);
        int to = __ldg(tgt_order + e);
        float4 sp = reinterpret_cast<const float4*>(g_sproj + ((size_t)b * NSRC + so) * DD)[lane];
        float4 tp = reinterpret_cast<const float4*>(g_tproj + ((size_t)b * NTGT + to) * DD)[lane];

        float z0 = silu_f(acc[r].x + sp.x + tp.x);
        float z1 = silu_f(acc[r].y + sp.y + tp.y);
        float z2 = silu_f(acc[r].z + sp.z + tp.z);
        float z3 = silu_f(acc[r].w + sp.w + tp.w);

        float mean, rstd;
        warp_ln_stats(z0, z1, z2, z3, mean, rstd);

        float4 db;
        db.x = (z0 - mean) * rstd * gv.x + bv.x;
        db.y = (z1 - mean) * rstd * gv.y + bv.y;
        db.z = (z2 - mean) * rstd * gv.z + bv.z;
        db.w = (z3 - mean) * rstd * gv.w + bv.w;

        reinterpret_cast<float4*>(g_dbond + row * DD)[lane] = db;

        float4 xin = reinterpret_cast<const float4*>(Xs + (warp * ROWS_PER_WARP + r) * DD)[lane];
        float4 ov;
        ov.x = xin.x + db.x; ov.y = xin.y + db.y;
        ov.z = xin.z + db.z; ov.w = xin.w + db.w;
        reinterpret_cast<float4*>(out_bond + row * DD)[lane] = ov;
    }
}

// ---------------- Kernel 3: node update ---------------------------------------
// br = mean_k coef[t,k] * d_bond[b, edge_order[t,k]]
// d_tgt = LN(silu(br@W_e2t + tproj2)) ; out_tgt = tgt + d_tgt
extern "C" __global__ void __launch_bounds__(256, 2)
k_node(const float* __restrict__ tgt, const float* __restrict__ W,
       const float* __restrict__ coef, const int* __restrict__ edge_order,
       const float* __restrict__ ln_g, const float* __restrict__ ln_b,
       float* __restrict__ out_tgt) {
    extern __shared__ float sm[];
    float* Ws = sm;
    float* Xs = sm + DD * DD;
    const int tid = threadIdx.x, lane = tid & 31, warp = tid >> 5;
    const size_t rowBase = (size_t)blockIdx.x * ROWS_PER_BLK;   // rows = b*NTGT + t

    load_w_smem(Ws, W, tid);

    // Phase A: gather-reduce bond_reduce rows into Xs
#pragma unroll
    for (int r = 0; r < ROWS_PER_WARP; ++r) {
        size_t row = rowBase + warp * ROWS_PER_WARP + r;
        int b = (int)(row / NTGT);
        int t = (int)(row - (size_t)b * NTGT);
        float4 acc4 = make_float4(0.f, 0.f, 0.f, 0.f);
#pragma unroll
        for (int k = 0; k < NK; ++k) {
            int e   = __ldg(edge_order + (size_t)t * NK + k);
            float c = __ldg(coef       + (size_t)t * NK + k);
            float4 v = reinterpret_cast<const float4*>(g_dbond + ((size_t)b * NE + e) * DD)[lane];
            acc4.x += c * v.x; acc4.y += c * v.y;
            acc4.z += c * v.z; acc4.w += c * v.w;
        }
        const float inv_k = 1.0f / NK;
        acc4.x *= inv_k; acc4.y *= inv_k; acc4.z *= inv_k; acc4.w *= inv_k;
        reinterpret_cast<float4*>(Xs + (warp * ROWS_PER_WARP + r) * DD)[lane] = acc4;
    }
    __syncthreads();

    float4 acc[ROWS_PER_WARP];
    gemm_tile(Ws, Xs, warp * ROWS_PER_WARP, lane, acc);

    const float4 gv = reinterpret_cast<const float4*>(ln_g)[lane];
    const float4 bv = reinterpret_cast<const float4*>(ln_b)[lane];

#pragma unroll
    for (int r = 0; r < ROWS_PER_WARP; ++r) {
        size_t row = rowBase + warp * ROWS_PER_WARP + r;
        float4 t2 = reinterpret_cast<const float4*>(g_tproj2 + row * DD)[lane];

        float z0 = silu_f(acc[r].x + t2.x);
        float z1 = silu_f(acc[r].y + t2.y);
        float z2 = silu_f(acc[r].z + t2.z);
        float z3 = silu_f(acc[r].w + t2.w);

        float mean, rstd;
        warp_ln_stats(z0, z1, z2, z3, mean, rstd);

        float4 d;
        d.x = (z0 - mean) * rstd * gv.x + bv.x;
        d.y = (z1 - mean) * rstd * gv.y + bv.y;
        d.z = (z2 - mean) * rstd * gv.z + bv.z;
        d.w = (z3 - mean) * rstd * gv.w + bv.w;

        float4 tin = reinterpret_cast<const float4*>(tgt + row * DD)[lane];
        float4 ov;
        ov.x = tin.x + d.x; ov.y = tin.y + d.y;
        ov.z = tin.z + d.z; ov.w = tin.w + d.w;
        reinterpret_cast<float4*>(out_tgt + row * DD)[lane] = ov;
    }
}

// ---------------- launch ------------------------------------------------------
extern "C" void kernel_launch(void* const* d_in, const int* in_sizes, int n_in,
                              void* d_out, int out_size) {
    const float* bond   = (const float*)d_in[0];
    const float* src    = (const float*)d_in[1];
    const float* tgt    = (const float*)d_in[2];
    const float* W_s2e  = (const float*)d_in[3];
    const float* W_t2e  = (const float*)d_in[4];
    const float* W_e2e  = (const float*)d_in[5];
    const float* ln1_g  = (const float*)d_in[6];
    const float* ln1_b  = (const float*)d_in[7];
    const float* W_e2t  = (const float*)d_in[8];
    const float* W_t2t  = (const float*)d_in[9];
    const float* ln2_g  = (const float*)d_in[10];
    const float* ln2_b  = (const float*)d_in[11];
    const float* coef   = (const float*)d_in[12];
    const int*   so     = (const int*)d_in[13];
    const int*   to     = (const int*)d_in[14];
    const int*   eo     = (const int*)d_in[15];

    float* out = (float*)d_out;
    float* out_bond = out;                                   // [4,160000,128]
    float* out_src  = out + (size_t)NB * NE * DD;            // [4,10000,128]
    float* out_tgt  = out_src + (size_t)NB * NSRC * DD;      // [4,10000,128]

    const size_t smem = SMEM_FLOATS * sizeof(float);         // 96 KB
    cudaFuncSetAttribute(k_gemm128, cudaFuncAttributeMaxDynamicSharedMemorySize, (int)smem);
    cudaFuncSetAttribute(k_bond,    cudaFuncAttributeMaxDynamicSharedMemorySize, (int)smem);
    cudaFuncSetAttribute(k_node,    cudaFuncAttributeMaxDynamicSharedMemorySize, (int)smem);

    float *sproj, *tproj, *tproj2;
    cudaGetSymbolAddress((void**)&sproj,  g_sproj);
    cudaGetSymbolAddress((void**)&tproj,  g_tproj);
    cudaGetSymbolAddress((void**)&tproj2, g_tproj2);

    // src pass-through (independent; issue first)
    cudaMemcpyAsync(out_src, src, (size_t)NB * NSRC * DD * sizeof(float),
                    cudaMemcpyDeviceToDevice);

    const int rowsNode = NB * NTGT;                          // 40000
    const int rowsBond = NB * NE;                            // 640000

    k_gemm128<<<rowsNode / ROWS_PER_BLK, 256, smem>>>(src, W_s2e, sproj);
    k_gemm128<<<rowsNode / ROWS_PER_BLK, 256, smem>>>(tgt, W_t2e, tproj);
    k_gemm128<<<rowsNode / ROWS_PER_BLK, 256, smem>>>(tgt, W_t2t, tproj2);

    k_bond<<<rowsBond / ROWS_PER_BLK, 256, smem>>>(bond, W_e2e, so, to,
                                                   ln1_g, ln1_b, out_bond);

    k_node<<<rowsNode / ROWS_PER_BLK, 256, smem>>>(tgt, W_e2t, coef, eo,
                                                   ln2_g, ln2_b, out_tgt);
}

// round 6
// speedup vs baseline: 1.1500x; 1.1500x over previous
#include <cuda_runtime.h>
#include <cstddef>

// Problem constants
#define DD   128
#define NB   4
#define NSRC 10000
#define NTGT 10000
#define NE   160000
#define NK   16

// Scratch (device globals: allocation-free rule)
__device__ float g_sproj [NB * NSRC * DD];
__device__ float g_tproj [NB * NTGT * DD];
__device__ float g_tproj2[NB * NTGT * DD];
__device__ float g_dbond [NB * NE * DD];

// Tiling: 256 threads = 8 warps; each warp owns 8 rows x (4 cols per lane).
#define ROWS_PER_WARP 8
#define ROWS_PER_BLK  64
#define XT_STRIDE     66                               // even (8B-aligned pairs) + conflict-breaking pad
#define SMEM_FLOATS   (DD * DD + DD * XT_STRIDE)       // W (16384) + X^T tile (8448)

typedef unsigned long long u64;

__device__ __forceinline__ float silu_f(float x) {
    return x / (1.0f + __expf(-x));
}

__device__ __forceinline__ u64 dup_f32x2(float w) {
    u64 r; asm("mov.b64 %0, {%1, %1};" : "=l"(r) : "f"(w)); return r;
}
__device__ __forceinline__ u64 ffma2(u64 a, u64 b, u64 c) {
    u64 d; asm("fma.rn.f32x2 %0, %1, %2, %3;" : "=l"(d) : "l"(a), "l"(b), "l"(c)); return d;
}
__device__ __forceinline__ void unpack2(u64 v, float& lo, float& hi) {
    asm("mov.b64 {%0, %1}, %2;" : "=f"(lo), "=f"(hi) : "l"(v));
}

__device__ __forceinline__ void load_w_smem(float* Ws, const float* __restrict__ W, int tid) {
    const float4* src = reinterpret_cast<const float4*>(W);
    float4* dst = reinterpret_cast<float4*>(Ws);
#pragma unroll
    for (int i = 0; i < 16; ++i)
        dst[tid + i * 256] = src[tid + i * 256];
}

// Load 64 rows x 128 cols from gmem, store TRANSPOSED: XsT[k * XT_STRIDE + row]
__device__ __forceinline__ void load_xT_smem(float* XsT, const float* __restrict__ Xrows, int tid) {
    const float4* src = reinterpret_cast<const float4*>(Xrows);
#pragma unroll
    for (int i = 0; i < 8; ++i) {
        int f  = tid + i * 256;       // float4 index (2048 total)
        int r  = f >> 5;              // row 0..63
        int kq = (f & 31) << 2;       // k 0..124 step 4
        float4 v = src[f];
        XsT[(kq + 0) * XT_STRIDE + r] = v.x;
        XsT[(kq + 1) * XT_STRIDE + r] = v.y;
        XsT[(kq + 2) * XT_STRIDE + r] = v.z;
        XsT[(kq + 3) * XT_STRIDE + r] = v.w;
    }
}

// FFMA2 GEMM tile: accf[r][c] = sum_k X[wrow0+r][k] * W[k][lane*4+c]
// Accumulators packed along row pairs: acc2[p][c] = (row 2p, row 2p+1)
__device__ __forceinline__ void gemm_tile2(const float* __restrict__ Ws,
                                           const float* __restrict__ XsT,
                                           int wrow0, int lane,
                                           float accf[ROWS_PER_WARP][4]) {
    u64 acc2[4][4];
#pragma unroll
    for (int p = 0; p < 4; ++p)
#pragma unroll
        for (int c = 0; c < 4; ++c) acc2[p][c] = 0ull;

#pragma unroll 4
    for (int k = 0; k < DD; ++k) {
        float4 wv = reinterpret_cast<const float4*>(Ws + k * DD)[lane];
        u64 w0 = dup_f32x2(wv.x);
        u64 w1 = dup_f32x2(wv.y);
        u64 w2 = dup_f32x2(wv.z);
        u64 w3 = dup_f32x2(wv.w);
        const float* xb = XsT + k * XT_STRIDE + wrow0;
#pragma unroll
        for (int p = 0; p < 4; ++p) {
            u64 xp = *reinterpret_cast<const u64*>(xb + 2 * p);   // broadcast LDS.64
            acc2[p][0] = ffma2(xp, w0, acc2[p][0]);
            acc2[p][1] = ffma2(xp, w1, acc2[p][1]);
            acc2[p][2] = ffma2(xp, w2, acc2[p][2]);
            acc2[p][3] = ffma2(xp, w3, acc2[p][3]);
        }
    }
#pragma unroll
    for (int p = 0; p < 4; ++p)
#pragma unroll
        for (int c = 0; c < 4; ++c)
            unpack2(acc2[p][c], accf[2 * p][c], accf[2 * p + 1][c]);
}

// In-warp LayerNorm stats over 128 values (4 per lane).
__device__ __forceinline__ void warp_ln_stats(float z0, float z1, float z2, float z3,
                                              float& mean, float& rstd) {
    float s  = z0 + z1 + z2 + z3;
    float s2 = z0 * z0 + z1 * z1 + z2 * z2 + z3 * z3;
#pragma unroll
    for (int off = 16; off; off >>= 1) {
        s  += __shfl_xor_sync(0xffffffffu, s,  off);
        s2 += __shfl_xor_sync(0xffffffffu, s2, off);
    }
    mean = s * (1.0f / DD);
    float var = s2 * (1.0f / DD) - mean * mean;
    rstd = rsqrtf(var + 1e-5f);
}

// ---------------- Kernel 1: plain Y = X @ W -----------------------------------
extern "C" __global__ void __launch_bounds__(256, 2)
k_gemm128(const float* __restrict__ X, const float* __restrict__ W, float* __restrict__ Y) {
    extern __shared__ float sm[];
    float* Ws  = sm;
    float* XsT = sm + DD * DD;
    const int tid = threadIdx.x, lane = tid & 31, warp = tid >> 5;
    const size_t rowBase = (size_t)blockIdx.x * ROWS_PER_BLK;

    load_w_smem(Ws, W, tid);
    load_xT_smem(XsT, X + rowBase * DD, tid);
    __syncthreads();

    float accf[ROWS_PER_WARP][4];
    gemm_tile2(Ws, XsT, warp * ROWS_PER_WARP, lane, accf);

#pragma unroll
    for (int r = 0; r < ROWS_PER_WARP; ++r) {
        size_t row = rowBase + warp * ROWS_PER_WARP + r;
        reinterpret_cast<float4*>(Y + row * DD)[lane] =
            make_float4(accf[r][0], accf[r][1], accf[r][2], accf[r][3]);
    }
}

// ---------------- Kernel 2: bond update ---------------------------------------
extern "C" __global__ void __launch_bounds__(256, 2)
k_bond(const float* __restrict__ bond, const float* __restrict__ W,
       const int* __restrict__ src_order, const int* __restrict__ tgt_order,
       const float* __restrict__ ln_g, const float* __restrict__ ln_b,
       float* __restrict__ out_bond) {
    extern __shared__ float sm[];
    float* Ws  = sm;
    float* XsT = sm + DD * DD;
    const int tid = threadIdx.x, lane = tid & 31, warp = tid >> 5;
    const size_t rowBase = (size_t)blockIdx.x * ROWS_PER_BLK;   // rows = b*NE + e

    load_w_smem(Ws, W, tid);
    load_xT_smem(XsT, bond + rowBase * DD, tid);
    __syncthreads();

    float accf[ROWS_PER_WARP][4];
    gemm_tile2(Ws, XsT, warp * ROWS_PER_WARP, lane, accf);

    const float4 gv = reinterpret_cast<const float4*>(ln_g)[lane];
    const float4 bv = reinterpret_cast<const float4*>(ln_b)[lane];

#pragma unroll
    for (int r = 0; r < ROWS_PER_WARP; ++r) {
        size_t row = rowBase + warp * ROWS_PER_WARP + r;
        int b = (int)(row / NE);
        int e = (int)(row - (size_t)b * NE);
        int so = __ldg(src_order + e);
        int to = __ldg(tgt_order + e);
        float4 sp = reinterpret_cast<const float4*>(g_sproj + ((size_t)b * NSRC + so) * DD)[lane];
        float4 tp = reinterpret_cast<const float4*>(g_tproj + ((size_t)b * NTGT + to) * DD)[lane];

        float z0 = silu_f(accf[r][0] + sp.x + tp.x);
        float z1 = silu_f(accf[r][1] + sp.y + tp.y);
        float z2 = silu_f(accf[r][2] + sp.z + tp.z);
        float z3 = silu_f(accf[r][3] + sp.w + tp.w);

        float mean, rstd;
        warp_ln_stats(z0, z1, z2, z3, mean, rstd);

        float4 db;
        db.x = (z0 - mean) * rstd * gv.x + bv.x;
        db.y = (z1 - mean) * rstd * gv.y + bv.y;
        db.z = (z2 - mean) * rstd * gv.z + bv.z;
        db.w = (z3 - mean) * rstd * gv.w + bv.w;

        reinterpret_cast<float4*>(g_dbond + row * DD)[lane] = db;

        float4 xin = reinterpret_cast<const float4*>(bond + row * DD)[lane];   // L1/L2 hit
        float4 ov;
        ov.x = xin.x + db.x; ov.y = xin.y + db.y;
        ov.z = xin.z + db.z; ov.w = xin.w + db.w;
        reinterpret_cast<float4*>(out_bond + row * DD)[lane] = ov;
    }
}

// ---------------- Kernel 3: node update ---------------------------------------
extern "C" __global__ void __launch_bounds__(256, 2)
k_node(const float* __restrict__ tgt, const float* __restrict__ W,
       const float* __restrict__ coef, const int* __restrict__ edge_order,
       const float* __restrict__ ln_g, const float* __restrict__ ln_b,
       float* __restrict__ out_tgt) {
    extern __shared__ float sm[];
    float* Ws  = sm;
    float* XsT = sm + DD * DD;
    const int tid = threadIdx.x, lane = tid & 31, warp = tid >> 5;
    const size_t rowBase = (size_t)blockIdx.x * ROWS_PER_BLK;   // rows = b*NTGT + t

    load_w_smem(Ws, W, tid);

    // Phase A: gather-reduce bond_reduce rows, write TRANSPOSED into XsT
#pragma unroll
    for (int r = 0; r < ROWS_PER_WARP; ++r) {
        int rl = warp * ROWS_PER_WARP + r;
        size_t row = rowBase + rl;
        int b = (int)(row / NTGT);
        int t = (int)(row - (size_t)b * NTGT);
        float4 acc4 = make_float4(0.f, 0.f, 0.f, 0.f);
#pragma unroll
        for (int k = 0; k < NK; ++k) {
            int e   = __ldg(edge_order + (size_t)t * NK + k);
            float c = __ldg(coef       + (size_t)t * NK + k);
            float4 v = reinterpret_cast<const float4*>(g_dbond + ((size_t)b * NE + e) * DD)[lane];
            acc4.x += c * v.x; acc4.y += c * v.y;
            acc4.z += c * v.z; acc4.w += c * v.w;
        }
        const float inv_k = 1.0f / NK;
        int k0 = lane * 4;
        XsT[(k0 + 0) * XT_STRIDE + rl] = acc4.x * inv_k;
        XsT[(k0 + 1) * XT_STRIDE + rl] = acc4.y * inv_k;
        XsT[(k0 + 2) * XT_STRIDE + rl] = acc4.z * inv_k;
        XsT[(k0 + 3) * XT_STRIDE + rl] = acc4.w * inv_k;
    }
    __syncthreads();

    float accf[ROWS_PER_WARP][4];
    gemm_tile2(Ws, XsT, warp * ROWS_PER_WARP, lane, accf);

    const float4 gv = reinterpret_cast<const float4*>(ln_g)[lane];
    const float4 bv = reinterpret_cast<const float4*>(ln_b)[lane];

#pragma unroll
    for (int r = 0; r < ROWS_PER_WARP; ++r) {
        size_t row = rowBase + warp * ROWS_PER_WARP + r;
        float4 t2 = reinterpret_cast<const float4*>(g_tproj2 + row * DD)[lane];

        float z0 = silu_f(accf[r][0] + t2.x);
        float z1 = silu_f(accf[r][1] + t2.y);
        float z2 = silu_f(accf[r][2] + t2.z);
        float z3 = silu_f(accf[r][3] + t2.w);

        float mean, rstd;
        warp_ln_stats(z0, z1, z2, z3, mean, rstd);

        float4 d;
        d.x = (z0 - mean) * rstd * gv.x + bv.x;
        d.y = (z1 - mean) * rstd * gv.y + bv.y;
        d.z = (z2 - mean) * rstd * gv.z + bv.z;
        d.w = (z3 - mean) * rstd * gv.w + bv.w;

        float4 tin = reinterpret_cast<const float4*>(tgt + row * DD)[lane];
        float4 ov;
        ov.x = tin.x + d.x; ov.y = tin.y + d.y;
        ov.z = tin.z + d.z; ov.w = tin.w + d.w;
        reinterpret_cast<float4*>(out_tgt + row * DD)[lane] = ov;
    }
}

// ---------------- launch ------------------------------------------------------
extern "C" void kernel_launch(void* const* d_in, const int* in_sizes, int n_in,
                              void* d_out, int out_size) {
    const float* bond   = (const float*)d_in[0];
    const float* src    = (const float*)d_in[1];
    const float* tgt    = (const float*)d_in[2];
    const float* W_s2e  = (const float*)d_in[3];
    const float* W_t2e  = (const float*)d_in[4];
    const float* W_e2e  = (const float*)d_in[5];
    const float* ln1_g  = (const float*)d_in[6];
    const float* ln1_b  = (const float*)d_in[7];
    const float* W_e2t  = (const float*)d_in[8];
    const float* W_t2t  = (const float*)d_in[9];
    const float* ln2_g  = (const float*)d_in[10];
    const float* ln2_b  = (const float*)d_in[11];
    const float* coef   = (const float*)d_in[12];
    const int*   so     = (const int*)d_in[13];
    const int*   to     = (const int*)d_in[14];
    const int*   eo     = (const int*)d_in[15];

    float* out = (float*)d_out;
    float* out_bond = out;                                   // [4,160000,128]
    float* out_src  = out + (size_t)NB * NE * DD;            // [4,10000,128]
    float* out_tgt  = out_src + (size_t)NB * NSRC * DD;      // [4,10000,128]

    const size_t smem = SMEM_FLOATS * sizeof(float);         // ~97 KB
    cudaFuncSetAttribute(k_gemm128, cudaFuncAttributeMaxDynamicSharedMemorySize, (int)smem);
    cudaFuncSetAttribute(k_bond,    cudaFuncAttributeMaxDynamicSharedMemorySize, (int)smem);
    cudaFuncSetAttribute(k_node,    cudaFuncAttributeMaxDynamicSharedMemorySize, (int)smem);

    float *sproj, *tproj, *tproj2;
    cudaGetSymbolAddress((void**)&sproj,  g_sproj);
    cudaGetSymbolAddress((void**)&tproj,  g_tproj);
    cudaGetSymbolAddress((void**)&tproj2, g_tproj2);

    // src pass-through (independent; issue first)
    cudaMemcpyAsync(out_src, src, (size_t)NB * NSRC * DD * sizeof(float),
                    cudaMemcpyDeviceToDevice);

    const int rowsNode = NB * NTGT;                          // 40000
    const int rowsBond = NB * NE;                            // 640000

    k_gemm128<<<rowsNode / ROWS_PER_BLK, 256, smem>>>(src, W_s2e, sproj);
    k_gemm128<<<rowsNode / ROWS_PER_BLK, 256, smem>>>(tgt, W_t2e, tproj);
    k_gemm128<<<rowsNode / ROWS_PER_BLK, 256, smem>>>(tgt, W_t2t, tproj2);

    k_bond<<<rowsBond / ROWS_PER_BLK, 256, smem>>>(bond, W_e2e, so, to,
                                                   ln1_g, ln1_b, out_bond);

    k_node<<<rowsNode / ROWS_PER_BLK, 256, smem>>>(tgt, W_e2t, coef, eo,
                                                   ln2_g, ln2_b, out_tgt);
}